// round 8
// baseline (speedup 1.0000x reference)
#include <cuda_runtime.h>
#include <cstdint>

#define NN 100000
#define NE 1600000
constexpr int IN_C  = 64;
constexpr int HID_C = 128;
constexpr int OUT_C = 64;

// ---------------- scratch (device globals; no allocation allowed) ----------------
__device__                int   g_is64;           // 1 if edge_index is int64-laid-out
__device__ __align__(16) float g_deg [NN];
__device__ __align__(16) float g_dinv[NN];
__device__ __align__(16) float g_agg1[(size_t)NN * IN_C];   // A_hat @ x
__device__ __align__(16) float g_h   [(size_t)NN * HID_C];  // relu(agg1 W3 + b3)
__device__ __align__(16) float g_hw  [(size_t)NN * OUT_C];  // h @ W4

__device__ __forceinline__ int clampi(int v, int lo, int hi) {
    return min(max(v, lo), hi);
}

// Probe layout: int64 little-endian with values < 2^31 has all odd 32-bit words == 0.
__global__ void k_detect(const int* __restrict__ ei32) {
    if (blockIdx.x == 0 && threadIdx.x == 0) {
        int all0 = 1;
        for (int i = 0; i < 256; i++) {
            if (ei32[2 * i + 1] != 0) { all0 = 0; break; }
        }
        g_is64 = all0;
    }
}

// index loads honoring detected layout
__device__ __forceinline__ int load_src(const int* __restrict__ ei32, int e, int ne, int is64) {
    return is64 ? ei32[(size_t)2 * e] : ei32[e];
}
__device__ __forceinline__ int load_dst(const int* __restrict__ ei32, int e, int ne, int is64) {
    return is64 ? ei32[(size_t)2 * (ne + e)] : ei32[(size_t)ne + e];
}

// ---------------- degree / norm prep ----------------
__global__ void k_init_deg(int n) {
    int i = blockIdx.x * blockDim.x + threadIdx.x;
    if (i < n) g_deg[i] = 1.0f;           // self-loop
}

__global__ void k_count_deg(const int* __restrict__ ei32, int ne, int n) {
    int e = blockIdx.x * blockDim.x + threadIdx.x;
    if (e < ne) {
        int is64 = g_is64;
        int d = clampi(load_dst(ei32, e, ne, is64), 0, n - 1);
        atomicAdd(&g_deg[d], 1.0f);       // scalar f32 RED: supported
    }
}

__global__ void k_dinv(int n) {
    int i = blockIdx.x * blockDim.x + threadIdx.x;
    if (i < n) g_dinv[i] = rsqrtf(g_deg[i]);
}

// ---------------- self-loop init: out[n] = dinv[n]^2 * feat[n] (+bias) ----------
template <bool BIAS>
__device__ __forceinline__ void self_body(const float* __restrict__ feat,
                                          float* __restrict__ outp,
                                          const float* __restrict__ bias, int n) {
    int t = blockIdx.x * blockDim.x + threadIdx.x;
    int node = t >> 4;
    int c4   = t & 15;
    if (node >= n) return;
    float di = g_dinv[node];
    float sc = di * di;
    float4 v = *(const float4*)(feat + (size_t)node * 64 + c4 * 4);
    v.x *= sc; v.y *= sc; v.z *= sc; v.w *= sc;
    if (BIAS) {
        float4 bv = *(const float4*)(bias + c4 * 4);
        v.x += bv.x; v.y += bv.y; v.z += bv.z; v.w += bv.w;
    }
    *(float4*)(outp + (size_t)node * 64 + c4 * 4) = v;
}

__global__ void k_self_l1(const float* __restrict__ x, int n) {
    self_body<false>(x, g_agg1, nullptr, n);
}

__global__ void k_self_l2(const float* __restrict__ b4, float* __restrict__ out, int n) {
    self_body<true>(g_hw, out, b4, n);
}

// ---------------- edge scatter: out[dst,c] += dinv[s]*dinv[d] * feat[src,c] ------
// One thread per (edge, channel): exactly ONE scalar atomicAdd per thread
// (nothing for ptxas to fuse into an unsupported vector RED).
__device__ __forceinline__ void scatter_body(const int* __restrict__ ei32,
                                             const float* __restrict__ feat,
                                             float* __restrict__ outp,
                                             int ne, int n) {
    long long t = (long long)blockIdx.x * blockDim.x + threadIdx.x;
    int e = (int)(t >> 6);
    int c = (int)(t & 63);
    if (e >= ne) return;
    int is64 = g_is64;
    int s = clampi(load_src(ei32, e, ne, is64), 0, n - 1);   // warp-uniform
    int d = clampi(load_dst(ei32, e, ne, is64), 0, n - 1);   // warp-uniform
    float w = g_dinv[s] * g_dinv[d];                          // warp-uniform
    float v = __ldg(feat + (size_t)s * 64 + c);               // coalesced 128B
    atomicAdd(outp + (size_t)d * 64 + c, w * v);              // coalesced 128B red
}

__global__ void k_scatter_l1(const int* __restrict__ ei32,
                             const float* __restrict__ x, int ne, int n) {
    scatter_body(ei32, x, g_agg1, ne, n);
}

__global__ void k_scatter_l2(const int* __restrict__ ei32,
                             float* __restrict__ out, int ne, int n) {
    scatter_body(ei32, g_hw, out, ne, n);
}

// ---------------- small dense GEMM: out[M,N] = (relu)(A[M,K] @ W[K,N] (+bias)) -----
template <int K, int N, bool RELU, bool BIAS>
__device__ __forceinline__ void gemm_body(const float* __restrict__ A,
                                          const float* __restrict__ W,
                                          const float* __restrict__ bias,
                                          float* __restrict__ out, int M) {
    constexpr int ROWS = 128;
    constexpr int KT   = 32;
    constexpr int CG   = N / 16;           // col groups
    constexpr int NT   = CG * (ROWS / 4);  // threads per block

    __shared__ __align__(16) float As[ROWS][KT + 4];
    __shared__ __align__(16) float Ws[KT][N];

    int tx = threadIdx.x;
    int cg = tx % CG;
    int rq = tx / CG;             // 0 .. ROWS/4-1
    int rb = blockIdx.x * ROWS;

    float acc[4][16];
#pragma unroll
    for (int r = 0; r < 4; r++)
#pragma unroll
        for (int j = 0; j < 16; j++) acc[r][j] = 0.0f;

    for (int kt = 0; kt < K; kt += KT) {
        for (int i = tx; i < ROWS * (KT / 4); i += NT) {
            int r  = i / (KT / 4);
            int kq = i % (KT / 4);
            int grow = rb + r;
            float4 v = (grow < M)
                ? *(const float4*)(A + (size_t)grow * K + kt + kq * 4)
                : make_float4(0.f, 0.f, 0.f, 0.f);
            As[r][kq * 4 + 0] = v.x;
            As[r][kq * 4 + 1] = v.y;
            As[r][kq * 4 + 2] = v.z;
            As[r][kq * 4 + 3] = v.w;
        }
        for (int i = tx; i < KT * (N / 4); i += NT) {
            int kk = i / (N / 4);
            int nq = i % (N / 4);
            *(float4*)&Ws[kk][nq * 4] = *(const float4*)(W + (size_t)(kt + kk) * N + nq * 4);
        }
        __syncthreads();

#pragma unroll
        for (int k = 0; k < KT; k++) {
            float xr[4];
#pragma unroll
            for (int r = 0; r < 4; r++) xr[r] = As[rq * 4 + r][k];
#pragma unroll
            for (int j = 0; j < 16; j += 4) {
                float4 wv = *(const float4*)&Ws[k][cg * 16 + j];
#pragma unroll
                for (int r = 0; r < 4; r++) {
                    acc[r][j + 0] += xr[r] * wv.x;
                    acc[r][j + 1] += xr[r] * wv.y;
                    acc[r][j + 2] += xr[r] * wv.z;
                    acc[r][j + 3] += xr[r] * wv.w;
                }
            }
        }
        __syncthreads();
    }

#pragma unroll
    for (int r = 0; r < 4; r++) {
        int grow = rb + rq * 4 + r;
        if (grow < M) {
#pragma unroll
            for (int j = 0; j < 16; j += 4) {
                float4 v;
                v.x = acc[r][j + 0]; v.y = acc[r][j + 1];
                v.z = acc[r][j + 2]; v.w = acc[r][j + 3];
                if (BIAS) {
                    v.x += bias[cg * 16 + j + 0];
                    v.y += bias[cg * 16 + j + 1];
                    v.z += bias[cg * 16 + j + 2];
                    v.w += bias[cg * 16 + j + 3];
                }
                if (RELU) {
                    v.x = fmaxf(v.x, 0.f); v.y = fmaxf(v.y, 0.f);
                    v.z = fmaxf(v.z, 0.f); v.w = fmaxf(v.w, 0.f);
                }
                *(float4*)(out + (size_t)grow * N + cg * 16 + j) = v;
            }
        }
    }
}

__global__ void k_gemm1(const float* __restrict__ W3, const float* __restrict__ b3, int M) {
    gemm_body<64, 128, true, true>(g_agg1, W3, b3, g_h, M);
}

__global__ void k_gemm2(const float* __restrict__ W4, int M) {
    gemm_body<128, 64, false, false>(g_h, W4, nullptr, g_hw, M);
}

// ---------------- launch ----------------
extern "C" void kernel_launch(void* const* d_in, const int* in_sizes, int n_in,
                              void* d_out, int out_size) {
    const float* x    = (const float*)d_in[0];
    const int*   ei32 = (const int*)d_in[1];     // int32 OR int64 layout; probed on device
    const float* W3   = (const float*)d_in[2];
    const float* b3   = (const float*)d_in[3];
    const float* W4   = (const float*)d_in[4];
    const float* b4   = (const float*)d_in[5];
    float* out = (float*)d_out;

    int nn = in_sizes[0] / IN_C;   // 100000
    int ne = in_sizes[1] / 2;      // 1600000 (elements of declared dtype / 2 rows)

    const int B  = 256;
    const int gN = (nn + B - 1) / B;
    const int gE = (ne + B - 1) / B;
    const int gS = (int)(((long long)nn * 16 + B - 1) / B);   // self kernels
    const int gX = (int)(((long long)ne * 64 + B - 1) / B);   // scatter kernels

    // dtype probe + degree/norm
    k_detect<<<1, 32>>>(ei32);
    k_init_deg<<<gN, B>>>(nn);
    k_count_deg<<<gE, B>>>(ei32, ne, nn);
    k_dinv<<<gN, B>>>(nn);

    // layer 1: agg1 = A_hat @ x ; h = relu(agg1 @ W3 + b3)
    k_self_l1<<<gS, B>>>(x, nn);
    k_scatter_l1<<<gX, B>>>(ei32, x, ne, nn);
    k_gemm1<<<(nn + 127) / 128, 256>>>(W3, b3, nn);

    // layer 2: hw = h @ W4 ; out = A_hat @ hw + b4
    k_gemm2<<<(nn + 127) / 128, 128>>>(W4, nn);
    k_self_l2<<<gS, B>>>(b4, out, nn);
    k_scatter_l2<<<gX, B>>>(ei32, out, ne, nn);
}

// round 10
// speedup vs baseline: 2.5833x; 2.5833x over previous
#include <cuda_runtime.h>
#include <cstdint>

#define NN 100000
#define NE 1600000
constexpr int IN_C  = 64;
constexpr int HID_C = 128;
constexpr int OUT_C = 64;

// ---------------- scratch (device globals; no allocation allowed) ----------------
__device__                int   g_is64;          // 1 if edge_index is int64-laid-out
__device__                int   g_total;         // slab allocator cursor
__device__ __align__(16) int   g_cnt [NN];      // in-degree (excl self)
__device__ __align__(16) int   g_rowS[NN];      // CSR slab start
__device__ __align__(16) int   g_cur [NN];      // fill cursor
__device__ __align__(16) float g_dinv[NN];
__device__ __align__(16) int2  g_csr [NE];      // {src, norm bits}
__device__ __align__(16) float g_agg1[(size_t)NN * IN_C];   // A_hat @ x
__device__ __align__(16) float g_h   [(size_t)NN * HID_C];  // relu(agg1 W3 + b3)
__device__ __align__(16) float g_hw  [(size_t)NN * OUT_C];  // h @ W4

__device__ __forceinline__ int clampi(int v, int lo, int hi) {
    return min(max(v, lo), hi);
}

// Probe layout: int64 little-endian with values < 2^31 has all odd 32-bit words == 0.
__global__ void k_detect(const int* __restrict__ ei32) {
    if (blockIdx.x == 0 && threadIdx.x == 0) {
        int all0 = 1;
        for (int i = 0; i < 256; i++) {
            if (ei32[2 * i + 1] != 0) { all0 = 0; break; }
        }
        g_is64 = all0;
    }
}

__device__ __forceinline__ int load_src(const int* __restrict__ ei32, int e, int ne, int is64) {
    return is64 ? ei32[(size_t)2 * e] : ei32[e];
}
__device__ __forceinline__ int load_dst(const int* __restrict__ ei32, int e, int ne, int is64) {
    return is64 ? ei32[(size_t)2 * (ne + e)] : ei32[(size_t)ne + e];
}

// ---------------- CSR build ----------------
__global__ void k_zero(int n) {
    int i = blockIdx.x * blockDim.x + threadIdx.x;
    if (i < n) g_cnt[i] = 0;
    if (i == 0) g_total = 0;
}

__global__ void k_hist(const int* __restrict__ ei32, int ne, int n) {
    int e = blockIdx.x * blockDim.x + threadIdx.x;
    if (e < ne) {
        int is64 = g_is64;
        int d = clampi(load_dst(ei32, e, ne, is64), 0, n - 1);
        atomicAdd(&g_cnt[d], 1);
    }
}

__global__ void k_dinv_alloc(int n) {
    int i = blockIdx.x * blockDim.x + threadIdx.x;
    if (i < n) {
        int c = g_cnt[i];
        g_dinv[i] = rsqrtf((float)(c + 1));       // +1 self-loop
        int r = atomicAdd(&g_total, c);           // slab (order-free)
        g_rowS[i] = r;
        g_cur[i]  = r;
    }
}

__global__ void k_fill(const int* __restrict__ ei32, int ne, int n) {
    int e = blockIdx.x * blockDim.x + threadIdx.x;
    if (e < ne) {
        int is64 = g_is64;
        int s = clampi(load_src(ei32, e, ne, is64), 0, n - 1);
        int d = clampi(load_dst(ei32, e, ne, is64), 0, n - 1);
        int pos = atomicAdd(&g_cur[d], 1);
        if (pos >= 0 && pos < ne) {
            float w = g_dinv[s] * g_dinv[d];
            g_csr[pos] = make_int2(s, __float_as_int(w));
        }
    }
}

// ---------------- aggregation (gather, no float atomics) -------------------------
// out[n] = dinv[n]^2 * feat[n] (+bias) + sum_{e in slab(n)} norm[e] * feat[src[e]]
// 16 threads per node; each owns 4 contiguous channels.
template <bool BIAS>
__device__ __forceinline__ void agg_body(const float* __restrict__ feat,
                                         float* __restrict__ outp,
                                         const float* __restrict__ bias, int n, int ne) {
    int t = blockIdx.x * blockDim.x + threadIdx.x;
    int node = t >> 4;
    int c4   = t & 15;
    if (node >= n) return;
    const float4* f4 = (const float4*)feat;

    float di = g_dinv[node];
    float sc = di * di;
    float4 acc = __ldg(f4 + (size_t)node * 16 + c4);
    acc.x *= sc; acc.y *= sc; acc.z *= sc; acc.w *= sc;
    if (BIAS) {
        float4 bv = *(const float4*)(bias + c4 * 4);
        acc.x += bv.x; acc.y += bv.y; acc.z += bv.z; acc.w += bv.w;
    }

    int beg = clampi(g_rowS[node], 0, ne);
    int end = clampi(beg + g_cnt[node], 0, ne);
    for (int k = beg; k < end; k++) {
        int2  en = __ldg(&g_csr[k]);               // broadcast within half-warp
        int   s  = clampi(en.x, 0, n - 1);
        float w  = __int_as_float(en.y);
        float4 v = __ldg(f4 + (size_t)s * 16 + c4);
        acc.x += w * v.x; acc.y += w * v.y;
        acc.z += w * v.z; acc.w += w * v.w;
    }
    *(float4*)(outp + (size_t)node * 64 + c4 * 4) = acc;
}

__global__ void k_agg_l1(const float* __restrict__ x, int n, int ne) {
    agg_body<false>(x, g_agg1, nullptr, n, ne);
}

__global__ void k_agg_l2(float* __restrict__ out, const float* __restrict__ b4, int n, int ne) {
    agg_body<true>(g_hw, out, b4, n, ne);
}

// ---------------- small dense GEMM: out[M,N] = (relu)(A[M,K] @ W[K,N] (+bias)) -----
template <int K, int N, bool RELU, bool BIAS>
__device__ __forceinline__ void gemm_body(const float* __restrict__ A,
                                          const float* __restrict__ W,
                                          const float* __restrict__ bias,
                                          float* __restrict__ out, int M) {
    constexpr int ROWS = 128;
    constexpr int KT   = 32;
    constexpr int CG   = N / 16;           // col groups
    constexpr int NT   = CG * (ROWS / 4);  // threads per block

    __shared__ __align__(16) float As[ROWS][KT + 4];
    __shared__ __align__(16) float Ws[KT][N];

    int tx = threadIdx.x;
    int cg = tx % CG;
    int rq = tx / CG;             // 0 .. ROWS/4-1
    int rb = blockIdx.x * ROWS;

    float acc[4][16];
#pragma unroll
    for (int r = 0; r < 4; r++)
#pragma unroll
        for (int j = 0; j < 16; j++) acc[r][j] = 0.0f;

    for (int kt = 0; kt < K; kt += KT) {
        for (int i = tx; i < ROWS * (KT / 4); i += NT) {
            int r  = i / (KT / 4);
            int kq = i % (KT / 4);
            int grow = rb + r;
            float4 v = (grow < M)
                ? *(const float4*)(A + (size_t)grow * K + kt + kq * 4)
                : make_float4(0.f, 0.f, 0.f, 0.f);
            As[r][kq * 4 + 0] = v.x;
            As[r][kq * 4 + 1] = v.y;
            As[r][kq * 4 + 2] = v.z;
            As[r][kq * 4 + 3] = v.w;
        }
        for (int i = tx; i < KT * (N / 4); i += NT) {
            int kk = i / (N / 4);
            int nq = i % (N / 4);
            *(float4*)&Ws[kk][nq * 4] = *(const float4*)(W + (size_t)(kt + kk) * N + nq * 4);
        }
        __syncthreads();

#pragma unroll
        for (int k = 0; k < KT; k++) {
            float xr[4];
#pragma unroll
            for (int r = 0; r < 4; r++) xr[r] = As[rq * 4 + r][k];
#pragma unroll
            for (int j = 0; j < 16; j += 4) {
                float4 wv = *(const float4*)&Ws[k][cg * 16 + j];
#pragma unroll
                for (int r = 0; r < 4; r++) {
                    acc[r][j + 0] += xr[r] * wv.x;
                    acc[r][j + 1] += xr[r] * wv.y;
                    acc[r][j + 2] += xr[r] * wv.z;
                    acc[r][j + 3] += xr[r] * wv.w;
                }
            }
        }
        __syncthreads();
    }

#pragma unroll
    for (int r = 0; r < 4; r++) {
        int grow = rb + rq * 4 + r;
        if (grow < M) {
#pragma unroll
            for (int j = 0; j < 16; j += 4) {
                float4 v;
                v.x = acc[r][j + 0]; v.y = acc[r][j + 1];
                v.z = acc[r][j + 2]; v.w = acc[r][j + 3];
                if (BIAS) {
                    v.x += bias[cg * 16 + j + 0];
                    v.y += bias[cg * 16 + j + 1];
                    v.z += bias[cg * 16 + j + 2];
                    v.w += bias[cg * 16 + j + 3];
                }
                if (RELU) {
                    v.x = fmaxf(v.x, 0.f); v.y = fmaxf(v.y, 0.f);
                    v.z = fmaxf(v.z, 0.f); v.w = fmaxf(v.w, 0.f);
                }
                *(float4*)(out + (size_t)grow * N + cg * 16 + j) = v;
            }
        }
    }
}

__global__ void k_gemm1(const float* __restrict__ W3, const float* __restrict__ b3, int M) {
    gemm_body<64, 128, true, true>(g_agg1, W3, b3, g_h, M);
}

__global__ void k_gemm2(const float* __restrict__ W4, int M) {
    gemm_body<128, 64, false, false>(g_h, W4, nullptr, g_hw, M);
}

// ---------------- launch ----------------
extern "C" void kernel_launch(void* const* d_in, const int* in_sizes, int n_in,
                              void* d_out, int out_size) {
    const float* x    = (const float*)d_in[0];
    const int*   ei32 = (const int*)d_in[1];     // int32 OR int64 layout; probed on device
    const float* W3   = (const float*)d_in[2];
    const float* b3   = (const float*)d_in[3];
    const float* W4   = (const float*)d_in[4];
    const float* b4   = (const float*)d_in[5];
    float* out = (float*)d_out;

    int nn = in_sizes[0] / IN_C;   // 100000
    int ne = in_sizes[1] / 2;      // 1600000

    const int B  = 256;
    const int gN = (nn + B - 1) / B;
    const int gE = (ne + B - 1) / B;
    const int gA = (int)(((long long)nn * 16 + B - 1) / B);

    // probe + CSR build
    k_detect<<<1, 32>>>(ei32);
    k_zero<<<gN, B>>>(nn);
    k_hist<<<gE, B>>>(ei32, ne, nn);
    k_dinv_alloc<<<gN, B>>>(nn);
    k_fill<<<gE, B>>>(ei32, ne, nn);

    // layer 1: agg1 = A_hat @ x ; h = relu(agg1 @ W3 + b3)
    k_agg_l1<<<gA, B>>>(x, nn, ne);
    k_gemm1<<<(nn + 127) / 128, 256>>>(W3, b3, nn);

    // layer 2: hw = h @ W4 ; out = A_hat @ hw + b4
    k_gemm2<<<(nn + 127) / 128, 128>>>(W4, nn);
    k_agg_l2<<<gA, B>>>(out, b4, nn, ne);
}

// round 11
// speedup vs baseline: 2.6348x; 1.0200x over previous
#include <cuda_runtime.h>
#include <cstdint>

#define NN 100000
#define NE 1600000
constexpr int IN_C  = 64;
constexpr int HID_C = 128;
constexpr int OUT_C = 64;

typedef unsigned long long u64;

// ---------------- scratch (device globals; no allocation allowed) ----------------
__device__                int   g_is64;          // 1 if edge_index is int64-laid-out
__device__                int   g_total;         // slab allocator cursor
__device__ __align__(16) int   g_cnt [NN];      // in-degree (excl self)
__device__ __align__(16) int   g_rowS[NN];      // CSR slab start
__device__ __align__(16) int   g_cur [NN];      // fill cursor
__device__ __align__(16) float g_dinv[NN];
__device__ __align__(16) int2  g_csr [NE];      // {src, norm bits}
__device__ __align__(16) float g_agg1[(size_t)NN * IN_C];   // A_hat @ x
__device__ __align__(16) float g_h   [(size_t)NN * HID_C];  // relu(agg1 W3 + b3)
__device__ __align__(16) float g_hw  [(size_t)NN * OUT_C];  // h @ W4

__device__ __forceinline__ int clampi(int v, int lo, int hi) {
    return min(max(v, lo), hi);
}

// ---------------- packed f32x2 helpers (Blackwell FFMA2 path) ----------------
__device__ __forceinline__ u64 pack2(float lo, float hi) {
    u64 r; asm("mov.b64 %0, {%1,%2};" : "=l"(r) : "f"(lo), "f"(hi)); return r;
}
__device__ __forceinline__ u64 fma2(u64 a, u64 b, u64 c) {
    u64 d; asm("fma.rn.f32x2 %0, %1, %2, %3;" : "=l"(d) : "l"(a), "l"(b), "l"(c)); return d;
}
__device__ __forceinline__ float2 unpack2(u64 v) {
    float2 f; asm("mov.b64 {%0,%1}, %2;" : "=f"(f.x), "=f"(f.y) : "l"(v)); return f;
}

// Probe layout: int64 little-endian with values < 2^31 has all odd 32-bit words == 0.
__global__ void k_detect(const int* __restrict__ ei32) {
    __shared__ int bad;
    if (threadIdx.x == 0) bad = 0;
    __syncthreads();
    if (ei32[2 * threadIdx.x + 1] != 0) bad = 1;
    __syncthreads();
    if (threadIdx.x == 0) g_is64 = bad ? 0 : 1;
}

__device__ __forceinline__ int load_src(const int* __restrict__ ei32, int e, int ne, int is64) {
    return is64 ? ei32[(size_t)2 * e] : ei32[e];
}
__device__ __forceinline__ int load_dst(const int* __restrict__ ei32, int e, int ne, int is64) {
    return is64 ? ei32[(size_t)2 * (ne + e)] : ei32[(size_t)ne + e];
}

// ---------------- CSR build ----------------
__global__ void k_zero(int n) {
    int i = blockIdx.x * blockDim.x + threadIdx.x;
    if (i < n) g_cnt[i] = 0;
    if (i == 0) g_total = 0;
}

__global__ void k_hist(const int* __restrict__ ei32, int ne, int n) {
    int e = blockIdx.x * blockDim.x + threadIdx.x;
    if (e < ne) {
        int is64 = g_is64;
        int d = clampi(load_dst(ei32, e, ne, is64), 0, n - 1);
        atomicAdd(&g_cnt[d], 1);
    }
}

__global__ void k_dinv_alloc(int n) {
    int i = blockIdx.x * blockDim.x + threadIdx.x;
    if (i < n) {
        int c = g_cnt[i];
        g_dinv[i] = rsqrtf((float)(c + 1));       // +1 self-loop
        int r = atomicAdd(&g_total, c);           // slab (order-free)
        g_rowS[i] = r;
        g_cur[i]  = r;
    }
}

__global__ void k_fill(const int* __restrict__ ei32, int ne, int n) {
    int e = blockIdx.x * blockDim.x + threadIdx.x;
    if (e < ne) {
        int is64 = g_is64;
        int s = clampi(load_src(ei32, e, ne, is64), 0, n - 1);
        int d = clampi(load_dst(ei32, e, ne, is64), 0, n - 1);
        int pos = atomicAdd(&g_cur[d], 1);
        if (pos >= 0 && pos < ne) {
            float w = g_dinv[s] * g_dinv[d];
            g_csr[pos] = make_int2(s, __float_as_int(w));
        }
    }
}

// ---------------- aggregation: warp per node, 2 edges in flight ------------------
// out[n] = dinv[n]^2 * feat[n] (+bias) + sum_{e in slab(n)} norm[e] * feat[src[e]]
// Lanes 0-15 handle even edges, 16-31 odd edges; shfl-combine, half 0 stores.
template <bool BIAS>
__device__ __forceinline__ void agg_body(const float* __restrict__ feat,
                                         float* __restrict__ outp,
                                         const float* __restrict__ bias, int n, int ne) {
    int t    = blockIdx.x * blockDim.x + threadIdx.x;
    int node = t >> 5;
    int lane = t & 31;
    int c4   = lane & 15;
    int half = lane >> 4;
    if (node >= n) return;
    const float4* f4 = (const float4*)feat;

    float4 acc = make_float4(0.f, 0.f, 0.f, 0.f);
    if (half == 0) {
        float di = g_dinv[node];
        float sc = di * di;
        float4 v = __ldg(f4 + (size_t)node * 16 + c4);
        acc.x = v.x * sc; acc.y = v.y * sc; acc.z = v.z * sc; acc.w = v.w * sc;
        if (BIAS) {
            float4 bv = *(const float4*)(bias + c4 * 4);
            acc.x += bv.x; acc.y += bv.y; acc.z += bv.z; acc.w += bv.w;
        }
    }

    int beg = clampi(g_rowS[node], 0, ne);
    int end = clampi(beg + g_cnt[node], 0, ne);
    for (int k = beg + half; k < end; k += 2) {
        int2  en = __ldg(&g_csr[k]);
        int   s  = clampi(en.x, 0, n - 1);
        float w  = __int_as_float(en.y);
        float4 v = __ldg(f4 + (size_t)s * 16 + c4);
        acc.x += w * v.x; acc.y += w * v.y;
        acc.z += w * v.z; acc.w += w * v.w;
    }

    acc.x += __shfl_down_sync(0xffffffffu, acc.x, 16);
    acc.y += __shfl_down_sync(0xffffffffu, acc.y, 16);
    acc.z += __shfl_down_sync(0xffffffffu, acc.z, 16);
    acc.w += __shfl_down_sync(0xffffffffu, acc.w, 16);

    if (half == 0)
        *(float4*)(outp + (size_t)node * 64 + c4 * 4) = acc;
}

__global__ void k_agg_l1(const float* __restrict__ x, int n, int ne) {
    agg_body<false>(x, g_agg1, nullptr, n, ne);
}

__global__ void k_agg_l2(float* __restrict__ out, const float* __restrict__ b4, int n, int ne) {
    agg_body<true>(g_hw, out, b4, n, ne);
}

// ---------------- dense GEMM with packed f32x2 FMA -------------------------------
// out[M,N] = (relu)(A[M,K] @ W[K,N] (+bias))
template <int K, int N, bool RELU, bool BIAS>
__device__ __forceinline__ void gemm_body(const float* __restrict__ A,
                                          const float* __restrict__ W,
                                          const float* __restrict__ bias,
                                          float* __restrict__ out, int M) {
    constexpr int ROWS = 128;
    constexpr int KT   = 32;
    constexpr int CG   = N / 16;           // col groups
    constexpr int NT   = CG * (ROWS / 4);  // threads per block

    __shared__ __align__(16) float As[ROWS][KT + 4];
    __shared__ __align__(16) float Ws[KT][N];

    int tx = threadIdx.x;
    int cg = tx % CG;
    int rq = tx / CG;             // 0 .. ROWS/4-1
    int rb = blockIdx.x * ROWS;

    u64 acc2[4][8];               // 4 rows x 16 cols as 8 packed f32x2
#pragma unroll
    for (int r = 0; r < 4; r++)
#pragma unroll
        for (int j = 0; j < 8; j++) acc2[r][j] = 0ULL;

    for (int kt = 0; kt < K; kt += KT) {
        for (int i = tx; i < ROWS * (KT / 4); i += NT) {
            int r  = i / (KT / 4);
            int kq = i % (KT / 4);
            int grow = rb + r;
            float4 v = (grow < M)
                ? *(const float4*)(A + (size_t)grow * K + kt + kq * 4)
                : make_float4(0.f, 0.f, 0.f, 0.f);
            As[r][kq * 4 + 0] = v.x;
            As[r][kq * 4 + 1] = v.y;
            As[r][kq * 4 + 2] = v.z;
            As[r][kq * 4 + 3] = v.w;
        }
        for (int i = tx; i < KT * (N / 4); i += NT) {
            int kk = i / (N / 4);
            int nq = i % (N / 4);
            *(float4*)&Ws[kk][nq * 4] = *(const float4*)(W + (size_t)(kt + kk) * N + nq * 4);
        }
        __syncthreads();

#pragma unroll
        for (int k = 0; k < KT; k++) {
            // W tile cols for this thread, read as packed u64 pairs (LDS.64/128)
            const u64* wp = (const u64*)&Ws[k][cg * 16];
            u64 wv[8];
#pragma unroll
            for (int j = 0; j < 8; j++) wv[j] = wp[j];
#pragma unroll
            for (int r = 0; r < 4; r++) {
                float xr = As[rq * 4 + r][k];
                u64 xp = pack2(xr, xr);
#pragma unroll
                for (int j = 0; j < 8; j++)
                    acc2[r][j] = fma2(xp, wv[j], acc2[r][j]);
            }
        }
        __syncthreads();
    }

#pragma unroll
    for (int r = 0; r < 4; r++) {
        int grow = rb + rq * 4 + r;
        if (grow < M) {
#pragma unroll
            for (int j = 0; j < 8; j += 2) {
                float2 lo = unpack2(acc2[r][j]);
                float2 hi = unpack2(acc2[r][j + 1]);
                float4 v  = make_float4(lo.x, lo.y, hi.x, hi.y);
                if (BIAS) {
                    v.x += bias[cg * 16 + j * 2 + 0];
                    v.y += bias[cg * 16 + j * 2 + 1];
                    v.z += bias[cg * 16 + j * 2 + 2];
                    v.w += bias[cg * 16 + j * 2 + 3];
                }
                if (RELU) {
                    v.x = fmaxf(v.x, 0.f); v.y = fmaxf(v.y, 0.f);
                    v.z = fmaxf(v.z, 0.f); v.w = fmaxf(v.w, 0.f);
                }
                *(float4*)(out + (size_t)grow * N + cg * 16 + j * 2) = v;
            }
        }
    }
}

__global__ void k_gemm1(const float* __restrict__ W3, const float* __restrict__ b3, int M) {
    gemm_body<64, 128, true, true>(g_agg1, W3, b3, g_h, M);
}

__global__ void k_gemm2(const float* __restrict__ W4, int M) {
    gemm_body<128, 64, false, false>(g_h, W4, nullptr, g_hw, M);
}

// ---------------- launch ----------------
extern "C" void kernel_launch(void* const* d_in, const int* in_sizes, int n_in,
                              void* d_out, int out_size) {
    const float* x    = (const float*)d_in[0];
    const int*   ei32 = (const int*)d_in[1];     // int32 OR int64 layout; probed on device
    const float* W3   = (const float*)d_in[2];
    const float* b3   = (const float*)d_in[3];
    const float* W4   = (const float*)d_in[4];
    const float* b4   = (const float*)d_in[5];
    float* out = (float*)d_out;

    int nn = in_sizes[0] / IN_C;   // 100000
    int ne = in_sizes[1] / 2;      // 1600000

    const int B  = 256;
    const int gN = (nn + B - 1) / B;
    const int gE = (ne + B - 1) / B;
    const int gA = (int)(((long long)nn * 32 + B - 1) / B);   // warp per node

    // probe + CSR build
    k_detect<<<1, 256>>>(ei32);
    k_zero<<<gN, B>>>(nn);
    k_hist<<<gE, B>>>(ei32, ne, nn);
    k_dinv_alloc<<<gN, B>>>(nn);
    k_fill<<<gE, B>>>(ei32, ne, nn);

    // layer 1: agg1 = A_hat @ x ; h = relu(agg1 @ W3 + b3)
    k_agg_l1<<<gA, B>>>(x, nn, ne);
    k_gemm1<<<(nn + 127) / 128, 256>>>(W3, b3, nn);

    // layer 2: hw = h @ W4 ; out = A_hat @ hw + b4
    k_gemm2<<<(nn + 127) / 128, 128>>>(W4, nn);
    k_agg_l2<<<gA, B>>>(out, b4, nn, ne);
}